// round 1
// baseline (speedup 1.0000x reference)
#include <cuda_runtime.h>

#define HW (1024 * 1024)
#define NB 16
#define BLOCKS_PER_BATCH 64
#define THREADS 256
#define EPS 1e-6f

// per-block partial sums: {S_p, S_pp, S_tp, S_t}
__device__ float4 g_partials[NB * BLOCKS_PER_BATCH];

__device__ __forceinline__ void accum(float l0, float l1, int t,
                                      float& sp, float& spp, float& stp, float& st) {
    // p1 = sigmoid(l1 - l0) = 1 / (1 + exp(l0 - l1))
    float e = __expf(l0 - l1);
    float p = __fdividef(1.0f, 1.0f + e);
    float tf = (t != 0) ? 1.0f : 0.0f;
    sp  += p;
    spp += p * p;
    stp += tf * p;
    st  += tf;
}

__global__ __launch_bounds__(THREADS)
void dice_partial_kernel(const float* __restrict__ logits,
                         const int* __restrict__ labels) {
    const int b   = blockIdx.x / BLOCKS_PER_BATCH;
    const int blk = blockIdx.x % BLOCKS_PER_BATCH;

    const float4* __restrict__ l0v = (const float4*)(logits + (size_t)b * 2 * HW);
    const float4* __restrict__ l1v = (const float4*)(logits + (size_t)b * 2 * HW + HW);
    const int4*   __restrict__ tv  = (const int4*)(labels + (size_t)b * HW);

    const int n4        = HW / 4;                  // 262144 float4 per plane
    const int per_block = n4 / BLOCKS_PER_BATCH;   // 4096
    const int base      = blk * per_block;

    float sp = 0.f, spp = 0.f, stp = 0.f, st = 0.f;

#pragma unroll 4
    for (int i = threadIdx.x; i < per_block; i += THREADS) {
        float4 a = l0v[base + i];
        float4 c = l1v[base + i];
        int4   t = tv[base + i];
        accum(a.x, c.x, t.x, sp, spp, stp, st);
        accum(a.y, c.y, t.y, sp, spp, stp, st);
        accum(a.z, c.z, t.z, sp, spp, stp, st);
        accum(a.w, c.w, t.w, sp, spp, stp, st);
    }

    // warp reduce
#pragma unroll
    for (int o = 16; o > 0; o >>= 1) {
        sp  += __shfl_down_sync(0xFFFFFFFFu, sp, o);
        spp += __shfl_down_sync(0xFFFFFFFFu, spp, o);
        stp += __shfl_down_sync(0xFFFFFFFFu, stp, o);
        st  += __shfl_down_sync(0xFFFFFFFFu, st, o);
    }

    __shared__ float4 sh[THREADS / 32];
    const int wid  = threadIdx.x >> 5;
    const int lane = threadIdx.x & 31;
    if (lane == 0) sh[wid] = make_float4(sp, spp, stp, st);
    __syncthreads();

    if (wid == 0) {
        float4 v = (lane < THREADS / 32) ? sh[lane] : make_float4(0.f, 0.f, 0.f, 0.f);
#pragma unroll
        for (int o = 4; o > 0; o >>= 1) {
            v.x += __shfl_down_sync(0xFFFFFFFFu, v.x, o);
            v.y += __shfl_down_sync(0xFFFFFFFFu, v.y, o);
            v.z += __shfl_down_sync(0xFFFFFFFFu, v.z, o);
            v.w += __shfl_down_sync(0xFFFFFFFFu, v.w, o);
        }
        if (lane == 0) g_partials[blockIdx.x] = v;
    }
}

__global__ __launch_bounds__(512)
void dice_final_kernel(float* __restrict__ out) {
    const int wid  = threadIdx.x >> 5;   // warp = batch
    const int lane = threadIdx.x & 31;

    __shared__ float sh[NB];

    float4 a = g_partials[wid * BLOCKS_PER_BATCH + lane];
    float4 b = g_partials[wid * BLOCKS_PER_BATCH + 32 + lane];
    float sp  = a.x + b.x;
    float spp = a.y + b.y;
    float stp = a.z + b.z;
    float st  = a.w + b.w;

#pragma unroll
    for (int o = 16; o > 0; o >>= 1) {
        sp  += __shfl_down_sync(0xFFFFFFFFu, sp, o);
        spp += __shfl_down_sync(0xFFFFFFFFu, spp, o);
        stp += __shfl_down_sync(0xFFFFFFFFu, stp, o);
        st  += __shfl_down_sync(0xFFFFFFFFu, st, o);
    }

    if (lane == 0) {
        const float N = (float)HW;
        // channel 1
        float num1 = 2.0f * stp;
        float den1 = spp + st;           // S_pp1 + S_tt1 (t^2 = t)
        // channel 0 (p0 = 1-p1, t0 = 1-t1)
        float num0 = 2.0f * (N - st - sp + stp);
        float den0 = (N - 2.0f * sp + spp) + (N - st);
        sh[wid] = num1 / (den1 + EPS) + num0 / (den0 + EPS);
    }
    __syncthreads();

    if (threadIdx.x == 0) {
        float s = 0.f;
#pragma unroll
        for (int i = 0; i < NB; i++) s += sh[i];
        out[0] = 1.0f - s / (float)(2 * NB);
    }
}

extern "C" void kernel_launch(void* const* d_in, const int* in_sizes, int n_in,
                              void* d_out, int out_size) {
    const float* logits = (const float*)d_in[0];
    const int*   labels = (const int*)d_in[1];
    float*       out    = (float*)d_out;

    dice_partial_kernel<<<NB * BLOCKS_PER_BATCH, THREADS>>>(logits, labels);
    dice_final_kernel<<<1, 512>>>(out);
}